// round 11
// baseline (speedup 1.0000x reference)
#include <cuda_runtime.h>
#include <cuda_bf16.h>

// Problem constants
#define B_   32
#define C_   256
#define HW_  64
#define NPLANES_ 8192        // B*C
#define HALF_PLANES_ 4096
#define HALF_B_ 16

// Scratch (device globals; no allocations allowed)
__device__ float g_rowmean[NPLANES_ * HW_];   // (B,C,H) mean over W
__device__ float g_colmean[NPLANES_ * HW_];   // (B,C,W) mean over H
__device__ float g_patchmean[NPLANES_ * 64];  // (B,C,8,8)
__device__ float g_hatt[NPLANES_ * HW_];
__device__ float g_watt[NPLANES_ * HW_];
__device__ float g_catt[B_ * C_];

// ---------------------------------------------------------------------------
// Block-wide reduce of two values (blockDim.x == 256 assumed)
// ---------------------------------------------------------------------------
__device__ __forceinline__ void blockReduce2(float& a, float& b) {
    #pragma unroll
    for (int o = 16; o; o >>= 1) {
        a += __shfl_xor_sync(0xffffffffu, a, o);
        b += __shfl_xor_sync(0xffffffffu, b, o);
    }
    __shared__ float sa[8], sb[8];
    int w = threadIdx.x >> 5, l = threadIdx.x & 31;
    if (l == 0) { sa[w] = a; sb[w] = b; }
    __syncthreads();
    if (w == 0) {
        a = (l < 8) ? sa[l] : 0.f;
        b = (l < 8) ? sb[l] : 0.f;
        #pragma unroll
        for (int o = 4; o; o >>= 1) {
            a += __shfl_xor_sync(0xffffffffu, a, o);
            b += __shfl_xor_sync(0xffffffffu, b, o);
        }
        if (l == 0) { sa[0] = a; sb[0] = b; }
    }
    __syncthreads();
    a = sa[0]; b = sb[0];
}

// ---------------------------------------------------------------------------
// K1: per-(b,c) plane: row means, col means, 8x8 patch means.
// (Verified-best geometry: 1 plane/block, regs=32, occ~91%.)
// ---------------------------------------------------------------------------
__global__ __launch_bounds__(256) void k1_reduce(const float* __restrict__ x,
                                                 int plane0) {
    __shared__ float sPatch[64 * 9];   // [h][pw], stride 9 (bank-spread)
    __shared__ float sCol[8 * 64];     // [warp][col]
    int plane = plane0 + blockIdx.x;
    const float4* xp = reinterpret_cast<const float4*>(x) + (size_t)plane * 1024;
    int tid = threadIdx.x;
    int lane = tid & 31, warp = tid >> 5, half = lane >> 4, l4 = lane & 15;

    float4 v[4];
    #pragma unroll
    for (int j = 0; j < 4; j++) v[j] = __ldg(&xp[tid + 256 * j]);

    // row sums + patch-row partials (extracted at level 1 of the tree)
    #pragma unroll
    for (int j = 0; j < 4; j++) {
        int h = warp * 2 + half + 16 * j;
        float s = (v[j].x + v[j].y) + (v[j].z + v[j].w);
        s += __shfl_xor_sync(0xffffffffu, s, 1);       // 8-col patch partial
        if ((l4 & 1) == 0) sPatch[h * 9 + (l4 >> 1)] = s;
        s += __shfl_xor_sync(0xffffffffu, s, 2);
        s += __shfl_xor_sync(0xffffffffu, s, 4);
        s += __shfl_xor_sync(0xffffffffu, s, 8);       // full row sum
        if (l4 == 0) g_rowmean[(size_t)plane * 64 + h] = s * (1.f / 64.f);
    }

    // col partials: accumulate the 4 rows in registers, fold halves via xor16
    float4 a;
    a.x = (v[0].x + v[1].x) + (v[2].x + v[3].x);
    a.y = (v[0].y + v[1].y) + (v[2].y + v[3].y);
    a.z = (v[0].z + v[1].z) + (v[2].z + v[3].z);
    a.w = (v[0].w + v[1].w) + (v[2].w + v[3].w);
    a.x += __shfl_xor_sync(0xffffffffu, a.x, 16);
    a.y += __shfl_xor_sync(0xffffffffu, a.y, 16);
    a.z += __shfl_xor_sync(0xffffffffu, a.z, 16);
    a.w += __shfl_xor_sync(0xffffffffu, a.w, 16);
    if (half == 0)
        *reinterpret_cast<float4*>(&sCol[warp * 64 + l4 * 4]) = a;
    __syncthreads();

    if (tid < 64) {
        float s = 0.f;
        #pragma unroll
        for (int w = 0; w < 8; w++) s += sCol[w * 64 + tid];
        g_colmean[(size_t)plane * 64 + tid] = s * (1.f / 64.f);
    } else if (tid < 128) {
        int pi = tid - 64, ph = pi >> 3, pw = pi & 7;
        float s = 0.f;
        #pragma unroll
        for (int r = 0; r < 8; r++) s += sPatch[(ph * 8 + r) * 9 + pw];
        g_patchmean[(size_t)plane * 64 + pi] = s * (1.f / 64.f);
    }
}

// ---------------------------------------------------------------------------
// KMID (per-half, 256 blocks): blocks 0..127   -> strip attention
//                              blocks 128..255 -> channel self-attention
// ---------------------------------------------------------------------------
__global__ __launch_bounds__(256) void kmid(
    const float* __restrict__ dw1, const float* __restrict__ db1,
    const float* __restrict__ dw2, const float* __restrict__ db2,
    const float* __restrict__ dw3, const float* __restrict__ db3,
    const float* __restrict__ dw4, const float* __restrict__ db4,
    const float* __restrict__ gnh_w, const float* __restrict__ gnh_b,
    const float* __restrict__ gnw_w, const float* __restrict__ gnw_b,
    const float* __restrict__ norm_w, const float* __restrict__ norm_b,
    const float* __restrict__ wq, const float* __restrict__ wk,
    const float* __restrict__ wv, int b0)
{
    __shared__ float smem[64 * 65];
    int bx = blockIdx.x;
    int tid = threadIdx.x;

    if (bx < 128) {
        // ----------------- strip attention path -----------------
        float* s = smem;
        int g = bx & 3, b = b0 + ((bx >> 2) & 15), axis = (bx >> 6) & 1;
        const float* src = (axis == 0 ? g_rowmean : g_colmean)
                           + ((size_t)(b * C_ + g * 64)) * 64;
        #pragma unroll
        for (int j = 0; j < 16; j++) {
            int p = tid + 256 * j;
            s[(p >> 6) * 65 + (p & 63)] = src[p];
        }
        __syncthreads();

        const float* wsel = (g == 0) ? dw1 : (g == 1) ? dw2 : (g == 2) ? dw3 : dw4;
        const float* bsel = (g == 0) ? db1 : (g == 1) ? db2 : (g == 2) ? db3 : db4;
        int k = 2 * g + 3, pad = g + 1;
        int ch = tid >> 2, l0 = (tid & 3) << 4;

        float wreg[9];
        #pragma unroll
        for (int j = 0; j < 9; j++) wreg[j] = (j < k) ? wsel[ch * k + j] : 0.f;
        float bias = bsel[ch];

        float out[16];
        float sum = 0.f, sq = 0.f;
        #pragma unroll
        for (int li = 0; li < 16; li++) {
            int l = l0 + li;
            float acc = bias;
            for (int j = 0; j < k; j++) {
                int sl = l + j - pad;
                if (sl >= 0 && sl < 64) acc += wreg[j] * s[ch * 65 + sl];
            }
            out[li] = acc;
            sum += acc; sq += acc * acc;
        }
        blockReduce2(sum, sq);
        float mean = sum * (1.f / 4096.f);
        float var  = sq  * (1.f / 4096.f) - mean * mean;
        float rstd = rsqrtf(var + 1e-5f);

        int gc = g * 64 + ch;
        float gamma = (axis == 0 ? gnh_w : gnw_w)[gc];
        float beta  = (axis == 0 ? gnh_b : gnw_b)[gc];
        float* dst = (axis == 0 ? g_hatt : g_watt)
                     + ((size_t)(b * C_ + gc)) * 64 + l0;
        #pragma unroll
        for (int li = 0; li < 16; li++) {
            float z = (out[li] - mean) * rstd * gamma + beta;
            dst[li] = 1.f / (1.f + __expf(-z));
        }
    } else {
        // ----------------- channel self-attention path -----------------
        int id = bx - 128;
        int b = b0 + (id >> 3), head = id & 7;
        const float* y0 = g_patchmean + (size_t)b * 16384;

        // batch GN(1) stats: float4-vectorized
        const float4* y0v = reinterpret_cast<const float4*>(y0);
        float sum = 0.f, sq = 0.f;
        #pragma unroll 4
        for (int i = 0; i < 16; i++) {
            float4 v = __ldg(&y0v[tid + 256 * i]);
            sum += (v.x + v.y) + (v.z + v.w);
            sq  += (v.x * v.x + v.y * v.y) + (v.z * v.z + v.w * v.w);
        }
        blockReduce2(sum, sq);
        float mu   = sum * (1.f / 16384.f);
        float rstd = rsqrtf(sq * (1.f / 16384.f) - mu * mu + 1e-5f);

        float* syT   = smem;                 // 64*33
        float* sS    = smem + 2112;          // 32*33
        float* svbar = smem + 2112 + 1056;   // 32

        #pragma unroll
        for (int i = 0; i < 8; i++) {
            int p = tid + 256 * i;
            int d = p >> 6, n = p & 63;
            int c = head * 32 + d;
            float v = (y0[(size_t)c * 64 + n] - mu) * rstd * norm_w[c] + norm_b[c];
            syT[n * 33 + d] = v;
        }
        __syncthreads();
        if (tid < 32) {
            float sm = 0.f;
            #pragma unroll
            for (int n = 0; n < 64; n++) sm += syT[n * 33 + tid];
            svbar[tid] = sm * (1.f / 64.f) * wv[head * 32 + tid];
        }
        __syncthreads();

        const float scale = 0.17677669529663689f;   // 32^-0.5
        int e  = tid & 31;
        int d0 = tid >> 5;
        float acc0 = 0.f, acc1 = 0.f, acc2 = 0.f, acc3 = 0.f;
        #pragma unroll 4
        for (int n = 0; n < 64; n++) {
            const float* row = &syT[n * 33];
            float bb = row[e];
            acc0 = fmaf(row[d0     ], bb, acc0);
            acc1 = fmaf(row[d0 +  8], bb, acc1);
            acc2 = fmaf(row[d0 + 16], bb, acc2);
            acc3 = fmaf(row[d0 + 24], bb, acc3);
        }
        float wke = wk[head * 32 + e] * scale;
        sS[(d0     ) * 33 + e] = acc0 * wq[head * 32 + d0     ] * wke;
        sS[(d0 +  8) * 33 + e] = acc1 * wq[head * 32 + d0 +  8] * wke;
        sS[(d0 + 16) * 33 + e] = acc2 * wq[head * 32 + d0 + 16] * wke;
        sS[(d0 + 24) * 33 + e] = acc3 * wq[head * 32 + d0 + 24] * wke;
        __syncthreads();

        if (tid < 32) {
            int d = tid;
            float m = -1e30f;
            #pragma unroll
            for (int j = 0; j < 32; j++) m = fmaxf(m, sS[d * 33 + j]);
            float ssum = 0.f, oacc = 0.f;
            #pragma unroll
            for (int j = 0; j < 32; j++) {
                float p = __expf(sS[d * 33 + j] - m);
                ssum += p; oacc += p * svbar[j];
            }
            float o = oacc / ssum;
            g_catt[b * C_ + head * 32 + d] = 1.f / (1.f + __expf(-o));
        }
    }
}

// ---------------------------------------------------------------------------
// K4: out = x * (h_att[h] * w_att[w] + c_att). 1 plane/block (k1 geometry).
// ---------------------------------------------------------------------------
__global__ __launch_bounds__(256) void k4_final(const float* __restrict__ x,
                                                float* __restrict__ out,
                                                int plane0) {
    __shared__ float sh[64], sw[64];
    __shared__ float sca;
    int plane = plane0 + blockIdx.x;
    int tid = threadIdx.x;
    const float4* xp = reinterpret_cast<const float4*>(x) + (size_t)plane * 1024;
    float4* op = reinterpret_cast<float4*>(out) + (size_t)plane * 1024;

    float4 v[4];
    #pragma unroll
    for (int j = 0; j < 4; j++) v[j] = __ldg(&xp[tid + 256 * j]);

    if (tid < 64)        sh[tid]      = g_hatt[(size_t)plane * 64 + tid];
    else if (tid < 128)  sw[tid - 64] = g_watt[(size_t)plane * 64 + tid - 64];
    else if (tid == 128) sca          = g_catt[plane];
    __syncthreads();

    float ca = sca;
    #pragma unroll
    for (int j = 0; j < 4; j++) {
        int p = tid + 256 * j;           // 0..1023
        int h = p >> 4, w4 = (p & 15) << 2;
        float hh = sh[h];
        float4 r;
        r.x = v[j].x * fmaf(hh, sw[w4 + 0], ca);
        r.y = v[j].y * fmaf(hh, sw[w4 + 1], ca);
        r.z = v[j].z * fmaf(hh, sw[w4 + 2], ca);
        r.w = v[j].w * fmaf(hh, sw[w4 + 3], ca);
        __stcs(&op[p], r);
    }
}

// ---------------------------------------------------------------------------
// Two-stream batch-half pipeline: h0 and h1 are independent (all reductions
// are per-batch). Fork from the launch stream via event, join at the end.
// Streams/events are created once on the first (non-captured) call; during
// graph capture the event edges become graph dependencies.
// ---------------------------------------------------------------------------
extern "C" void kernel_launch(void* const* d_in, const int* in_sizes, int n_in,
                              void* d_out, int out_size) {
    const float* x     = (const float*)d_in[0];
    const float* dw1   = (const float*)d_in[1];
    const float* db1   = (const float*)d_in[2];
    const float* dw2   = (const float*)d_in[3];
    const float* db2   = (const float*)d_in[4];
    const float* dw3   = (const float*)d_in[5];
    const float* db3   = (const float*)d_in[6];
    const float* dw4   = (const float*)d_in[7];
    const float* db4   = (const float*)d_in[8];
    const float* gnh_w = (const float*)d_in[9];
    const float* gnh_b = (const float*)d_in[10];
    const float* gnw_w = (const float*)d_in[11];
    const float* gnw_b = (const float*)d_in[12];
    const float* nrm_w = (const float*)d_in[13];
    const float* nrm_b = (const float*)d_in[14];
    const float* wq    = (const float*)d_in[15];
    const float* wk    = (const float*)d_in[16];
    const float* wv    = (const float*)d_in[17];
    float* out = (float*)d_out;

    static cudaStream_t st[2];
    static cudaEvent_t evFork, evJoin[2];
    static bool inited = false;
    if (!inited) {
        cudaStreamCreateWithFlags(&st[0], cudaStreamNonBlocking);
        cudaStreamCreateWithFlags(&st[1], cudaStreamNonBlocking);
        cudaEventCreateWithFlags(&evFork, cudaEventDisableTiming);
        cudaEventCreateWithFlags(&evJoin[0], cudaEventDisableTiming);
        cudaEventCreateWithFlags(&evJoin[1], cudaEventDisableTiming);
        inited = true;
    }

    cudaEventRecord(evFork, 0);
    for (int h = 0; h < 2; h++) {
        cudaStreamWaitEvent(st[h], evFork, 0);
        int plane0 = h * HALF_PLANES_;
        int b0 = h * HALF_B_;
        k1_reduce<<<HALF_PLANES_, 256, 0, st[h]>>>(x, plane0);
        kmid<<<256, 256, 0, st[h]>>>(dw1, db1, dw2, db2, dw3, db3, dw4, db4,
                                     gnh_w, gnh_b, gnw_w, gnw_b,
                                     nrm_w, nrm_b, wq, wk, wv, b0);
        k4_final<<<HALF_PLANES_, 256, 0, st[h]>>>(x, out, plane0);
        cudaEventRecord(evJoin[h], st[h]);
    }
    cudaStreamWaitEvent(0, evJoin[0], 0);
    cudaStreamWaitEvent(0, evJoin[1], 0);
}

// round 12
// speedup vs baseline: 1.0763x; 1.0763x over previous
#include <cuda_runtime.h>
#include <cuda_bf16.h>

// Problem constants
#define B_   32
#define C_   256
#define HW_  64
#define NPLANES_ 8192        // B*C

// Scratch (device globals; no allocations allowed)
__device__ float g_rowmean[NPLANES_ * HW_];   // (B,C,H) mean over W
__device__ float g_colmean[NPLANES_ * HW_];   // (B,C,W) mean over H
__device__ float g_patchmean[NPLANES_ * 64];  // (B,C,8,8)
__device__ float g_hatt[NPLANES_ * HW_];
__device__ float g_watt[NPLANES_ * HW_];
__device__ float g_catt[B_ * C_];

// ---------------------------------------------------------------------------
// Block-wide reduce of two values (blockDim.x == 256 assumed)
// ---------------------------------------------------------------------------
__device__ __forceinline__ void blockReduce2(float& a, float& b) {
    #pragma unroll
    for (int o = 16; o; o >>= 1) {
        a += __shfl_xor_sync(0xffffffffu, a, o);
        b += __shfl_xor_sync(0xffffffffu, b, o);
    }
    __shared__ float sa[8], sb[8];
    int w = threadIdx.x >> 5, l = threadIdx.x & 31;
    if (l == 0) { sa[w] = a; sb[w] = b; }
    __syncthreads();
    if (w == 0) {
        a = (l < 8) ? sa[l] : 0.f;
        b = (l < 8) ? sb[l] : 0.f;
        #pragma unroll
        for (int o = 4; o; o >>= 1) {
            a += __shfl_xor_sync(0xffffffffu, a, o);
            b += __shfl_xor_sync(0xffffffffu, b, o);
        }
        if (l == 0) { sa[0] = a; sb[0] = b; }
    }
    __syncthreads();
    a = sa[0]; b = sb[0];
}

// ---------------------------------------------------------------------------
// K1: per-(b,c) plane: row means, col means, 8x8 patch means.
// (Verified-best geometry: 1 plane/block, regs=32, occ~91%, 5.9 TB/s.)
// ---------------------------------------------------------------------------
__global__ __launch_bounds__(256) void k1_reduce(const float* __restrict__ x) {
    __shared__ float sPatch[64 * 9];   // [h][pw], stride 9 (bank-spread)
    __shared__ float sCol[8 * 64];     // [warp][col]
    int plane = blockIdx.x;
    const float4* xp = reinterpret_cast<const float4*>(x) + (size_t)plane * 1024;
    int tid = threadIdx.x;
    int lane = tid & 31, warp = tid >> 5, half = lane >> 4, l4 = lane & 15;

    float4 v[4];
    #pragma unroll
    for (int j = 0; j < 4; j++) v[j] = __ldg(&xp[tid + 256 * j]);

    // row sums + patch-row partials (extracted at level 1 of the tree)
    #pragma unroll
    for (int j = 0; j < 4; j++) {
        int h = warp * 2 + half + 16 * j;
        float s = (v[j].x + v[j].y) + (v[j].z + v[j].w);
        s += __shfl_xor_sync(0xffffffffu, s, 1);       // 8-col patch partial
        if ((l4 & 1) == 0) sPatch[h * 9 + (l4 >> 1)] = s;
        s += __shfl_xor_sync(0xffffffffu, s, 2);
        s += __shfl_xor_sync(0xffffffffu, s, 4);
        s += __shfl_xor_sync(0xffffffffu, s, 8);       // full row sum
        if (l4 == 0) g_rowmean[(size_t)plane * 64 + h] = s * (1.f / 64.f);
    }

    // col partials: accumulate the 4 rows in registers, fold halves via xor16
    float4 a;
    a.x = (v[0].x + v[1].x) + (v[2].x + v[3].x);
    a.y = (v[0].y + v[1].y) + (v[2].y + v[3].y);
    a.z = (v[0].z + v[1].z) + (v[2].z + v[3].z);
    a.w = (v[0].w + v[1].w) + (v[2].w + v[3].w);
    a.x += __shfl_xor_sync(0xffffffffu, a.x, 16);
    a.y += __shfl_xor_sync(0xffffffffu, a.y, 16);
    a.z += __shfl_xor_sync(0xffffffffu, a.z, 16);
    a.w += __shfl_xor_sync(0xffffffffu, a.w, 16);
    if (half == 0)
        *reinterpret_cast<float4*>(&sCol[warp * 64 + l4 * 4]) = a;
    __syncthreads();

    if (tid < 64) {
        float s = 0.f;
        #pragma unroll
        for (int w = 0; w < 8; w++) s += sCol[w * 64 + tid];
        g_colmean[(size_t)plane * 64 + tid] = s * (1.f / 64.f);
    } else if (tid < 128) {
        int pi = tid - 64, ph = pi >> 3, pw = pi & 7;
        float s = 0.f;
        #pragma unroll
        for (int r = 0; r < 8; r++) s += sPatch[(ph * 8 + r) * 9 + pw];
        g_patchmean[(size_t)plane * 64 + pi] = s * (1.f / 64.f);
    }
}

// ---------------------------------------------------------------------------
// KMID: fused. Blocks 0..255  -> strip attention.
//              Blocks 256..511 -> channel self-attention.
// Launched with PDL: waits on k1 via cudaGridDependencySynchronize().
// ---------------------------------------------------------------------------
__global__ __launch_bounds__(256) void kmid(
    const float* __restrict__ dw1, const float* __restrict__ db1,
    const float* __restrict__ dw2, const float* __restrict__ db2,
    const float* __restrict__ dw3, const float* __restrict__ db3,
    const float* __restrict__ dw4, const float* __restrict__ db4,
    const float* __restrict__ gnh_w, const float* __restrict__ gnh_b,
    const float* __restrict__ gnw_w, const float* __restrict__ gnw_b,
    const float* __restrict__ norm_w, const float* __restrict__ norm_b,
    const float* __restrict__ wq, const float* __restrict__ wk,
    const float* __restrict__ wv)
{
    __shared__ float smem[64 * 65];
    int bx = blockIdx.x;
    int tid = threadIdx.x;

#if __CUDA_ARCH__ >= 900
    cudaGridDependencySynchronize();   // wait for k1's writes
#endif

    if (bx < 256) {
        // ----------------- strip attention path -----------------
        float* s = smem;
        int g = bx & 3, b = (bx >> 2) & 31, axis = bx >> 7;
        const float* src = (axis == 0 ? g_rowmean : g_colmean)
                           + ((size_t)(b * C_ + g * 64)) * 64;
        #pragma unroll
        for (int j = 0; j < 16; j++) {
            int p = tid + 256 * j;
            s[(p >> 6) * 65 + (p & 63)] = src[p];
        }
        __syncthreads();

        const float* wsel = (g == 0) ? dw1 : (g == 1) ? dw2 : (g == 2) ? dw3 : dw4;
        const float* bsel = (g == 0) ? db1 : (g == 1) ? db2 : (g == 2) ? db3 : db4;
        int k = 2 * g + 3, pad = g + 1;
        int ch = tid >> 2, l0 = (tid & 3) << 4;

        float wreg[9];
        #pragma unroll
        for (int j = 0; j < 9; j++) wreg[j] = (j < k) ? wsel[ch * k + j] : 0.f;
        float bias = bsel[ch];

        float out[16];
        float sum = 0.f, sq = 0.f;
        #pragma unroll
        for (int li = 0; li < 16; li++) {
            int l = l0 + li;
            float acc = bias;
            for (int j = 0; j < k; j++) {
                int sl = l + j - pad;
                if (sl >= 0 && sl < 64) acc += wreg[j] * s[ch * 65 + sl];
            }
            out[li] = acc;
            sum += acc; sq += acc * acc;
        }
        blockReduce2(sum, sq);
        float mean = sum * (1.f / 4096.f);
        float var  = sq  * (1.f / 4096.f) - mean * mean;
        float rstd = rsqrtf(var + 1e-5f);

        int gc = g * 64 + ch;
        float gamma = (axis == 0 ? gnh_w : gnw_w)[gc];
        float beta  = (axis == 0 ? gnh_b : gnw_b)[gc];
        float* dst = (axis == 0 ? g_hatt : g_watt)
                     + ((size_t)(b * C_ + gc)) * 64 + l0;
        #pragma unroll
        for (int li = 0; li < 16; li++) {
            float z = (out[li] - mean) * rstd * gamma + beta;
            dst[li] = 1.f / (1.f + __expf(-z));
        }
    } else {
        // ----------------- channel self-attention path -----------------
        int id = bx - 256;
        int b = id >> 3, head = id & 7;
        const float* y0 = g_patchmean + (size_t)b * 16384;

        // batch GN(1) stats: float4-vectorized
        const float4* y0v = reinterpret_cast<const float4*>(y0);
        float sum = 0.f, sq = 0.f;
        #pragma unroll 4
        for (int i = 0; i < 16; i++) {
            float4 v = __ldg(&y0v[tid + 256 * i]);
            sum += (v.x + v.y) + (v.z + v.w);
            sq  += (v.x * v.x + v.y * v.y) + (v.z * v.z + v.w * v.w);
        }
        blockReduce2(sum, sq);
        float mu   = sum * (1.f / 16384.f);
        float rstd = rsqrtf(sq * (1.f / 16384.f) - mu * mu + 1e-5f);

        float* syT   = smem;                 // 64*33
        float* sS    = smem + 2112;          // 32*33
        float* svbar = smem + 2112 + 1056;   // 32

        #pragma unroll
        for (int i = 0; i < 8; i++) {
            int p = tid + 256 * i;
            int d = p >> 6, n = p & 63;
            int c = head * 32 + d;
            float v = (y0[(size_t)c * 64 + n] - mu) * rstd * norm_w[c] + norm_b[c];
            syT[n * 33 + d] = v;
        }
        __syncthreads();
        if (tid < 32) {
            float sm = 0.f;
            #pragma unroll
            for (int n = 0; n < 64; n++) sm += syT[n * 33 + tid];
            svbar[tid] = sm * (1.f / 64.f) * wv[head * 32 + tid];
        }
        __syncthreads();

        const float scale = 0.17677669529663689f;   // 32^-0.5
        int e  = tid & 31;
        int d0 = tid >> 5;
        float acc0 = 0.f, acc1 = 0.f, acc2 = 0.f, acc3 = 0.f;
        #pragma unroll 4
        for (int n = 0; n < 64; n++) {
            const float* row = &syT[n * 33];
            float bb = row[e];
            acc0 = fmaf(row[d0     ], bb, acc0);
            acc1 = fmaf(row[d0 +  8], bb, acc1);
            acc2 = fmaf(row[d0 + 16], bb, acc2);
            acc3 = fmaf(row[d0 + 24], bb, acc3);
        }
        float wke = wk[head * 32 + e] * scale;
        sS[(d0     ) * 33 + e] = acc0 * wq[head * 32 + d0     ] * wke;
        sS[(d0 +  8) * 33 + e] = acc1 * wq[head * 32 + d0 +  8] * wke;
        sS[(d0 + 16) * 33 + e] = acc2 * wq[head * 32 + d0 + 16] * wke;
        sS[(d0 + 24) * 33 + e] = acc3 * wq[head * 32 + d0 + 24] * wke;
        __syncthreads();

        if (tid < 32) {
            int d = tid;
            float m = -1e30f;
            #pragma unroll
            for (int j = 0; j < 32; j++) m = fmaxf(m, sS[d * 33 + j]);
            float ssum = 0.f, oacc = 0.f;
            #pragma unroll
            for (int j = 0; j < 32; j++) {
                float p = __expf(sS[d * 33 + j] - m);
                ssum += p; oacc += p * svbar[j];
            }
            float o = oacc / ssum;
            g_catt[b * C_ + head * 32 + d] = 1.f / (1.f + __expf(-o));
        }
    }
}

// ---------------------------------------------------------------------------
// K4: out = x * (h_att[h] * w_att[w] + c_att). 1 plane/block (k1 geometry).
// PDL: the 4 x-loads (independent of kmid) are issued BEFORE the dependency
// sync, so they stream from DRAM while kmid is still running.
// ---------------------------------------------------------------------------
__global__ __launch_bounds__(256) void k4_final(const float* __restrict__ x,
                                                float* __restrict__ out) {
    __shared__ float sh[64], sw[64];
    __shared__ float sca;
    int plane = (NPLANES_ - 1) - blockIdx.x;    // reverse order
    int tid = threadIdx.x;
    const float4* xp = reinterpret_cast<const float4*>(x) + (size_t)plane * 1024;
    float4* op = reinterpret_cast<float4*>(out) + (size_t)plane * 1024;

    float4 v[4];
    #pragma unroll
    for (int j = 0; j < 4; j++) v[j] = __ldg(&xp[tid + 256 * j]);

#if __CUDA_ARCH__ >= 900
    cudaGridDependencySynchronize();   // wait for kmid's writes
#endif

    if (tid < 64)        sh[tid]      = g_hatt[(size_t)plane * 64 + tid];
    else if (tid < 128)  sw[tid - 64] = g_watt[(size_t)plane * 64 + tid - 64];
    else if (tid == 128) sca          = g_catt[plane];
    __syncthreads();

    float ca = sca;
    #pragma unroll
    for (int j = 0; j < 4; j++) {
        int p = tid + 256 * j;           // 0..1023
        int h = p >> 4, w4 = (p & 15) << 2;
        float hh = sh[h];
        float4 r;
        r.x = v[j].x * fmaf(hh, sw[w4 + 0], ca);
        r.y = v[j].y * fmaf(hh, sw[w4 + 1], ca);
        r.z = v[j].z * fmaf(hh, sw[w4 + 2], ca);
        r.w = v[j].w * fmaf(hh, sw[w4 + 3], ca);
        __stcs(&op[p], r);
    }
}

// ---------------------------------------------------------------------------
extern "C" void kernel_launch(void* const* d_in, const int* in_sizes, int n_in,
                              void* d_out, int out_size) {
    const float* x     = (const float*)d_in[0];
    const float* dw1   = (const float*)d_in[1];
    const float* db1   = (const float*)d_in[2];
    const float* dw2   = (const float*)d_in[3];
    const float* db2   = (const float*)d_in[4];
    const float* dw3   = (const float*)d_in[5];
    const float* db3   = (const float*)d_in[6];
    const float* dw4   = (const float*)d_in[7];
    const float* db4   = (const float*)d_in[8];
    const float* gnh_w = (const float*)d_in[9];
    const float* gnh_b = (const float*)d_in[10];
    const float* gnw_w = (const float*)d_in[11];
    const float* gnw_b = (const float*)d_in[12];
    const float* nrm_w = (const float*)d_in[13];
    const float* nrm_b = (const float*)d_in[14];
    const float* wq    = (const float*)d_in[15];
    const float* wk    = (const float*)d_in[16];
    const float* wv    = (const float*)d_in[17];
    float* out = (float*)d_out;

    // k1: normal launch
    k1_reduce<<<NPLANES_, 256>>>(x);

    // kmid + k4: programmatic stream serialization (PDL overlap)
    cudaLaunchAttribute attr[1];
    attr[0].id = cudaLaunchAttributeProgrammaticStreamSerialization;
    attr[0].val.programmaticStreamSerializationAllowed = 1;

    {
        cudaLaunchConfig_t cfg = {};
        cfg.gridDim = dim3(512, 1, 1);
        cfg.blockDim = dim3(256, 1, 1);
        cfg.stream = 0;
        cfg.attrs = attr;
        cfg.numAttrs = 1;
        cudaLaunchKernelEx(&cfg, kmid,
                           dw1, db1, dw2, db2, dw3, db3, dw4, db4,
                           gnh_w, gnh_b, gnw_w, gnw_b,
                           nrm_w, nrm_b, wq, wk, wv);
    }
    {
        cudaLaunchConfig_t cfg = {};
        cfg.gridDim = dim3(NPLANES_, 1, 1);
        cfg.blockDim = dim3(256, 1, 1);
        cfg.stream = 0;
        cfg.attrs = attr;
        cfg.numAttrs = 1;
        cudaLaunchKernelEx(&cfg, k4_final, x, out);
    }
}